// round 1
// baseline (speedup 1.0000x reference)
#include <cuda_runtime.h>
#include <math.h>

#define LSEQ 1024
#define DMODEL 2048
#define NHQ 16
#define NHK 8
#define DHEAD 128
#define NCHUNK 16
#define CLEN 64
#define NITER 30
#define RIDGE_C 0.02f

// ---------------- device scratch ----------------
__device__ float g_pq[LSEQ * 2048];
__device__ float g_pk[LSEQ * 1024];
__device__ float g_pv[LSEQ * 1024];
__device__ float g_q [LSEQ * 2048];
__device__ float g_k [LSEQ * 1024];
__device__ float g_v [LSEQ * 1024];
__device__ float g_gp[LSEQ * 2048];
__device__ float g_glog [LSEQ * NHQ];
__device__ float g_beta [LSEQ * NHQ];
__device__ float g_alpha[LSEQ * NHQ];
__device__ float g_cs[NHQ * NCHUNK * CLEN];
__device__ float g_G [NHQ * NCHUNK];
__device__ float g_dgv[NHQ * NCHUNK];
__device__ float g_dH[NHQ * NCHUNK * DHEAD * DHEAD];
__device__ float g_dB[NHQ * NCHUNK * DHEAD * DHEAD];
__device__ float g_H0[NHQ * NCHUNK * DHEAD * DHEAD];
__device__ float g_B0[NHQ * NCHUNK * DHEAD * DHEAD];
__device__ float g_X [NHQ * NCHUNK * DHEAD * DHEAD];
__device__ float g_o [LSEQ * NHQ * DHEAD];
__device__ float g_on[LSEQ * 2048];

// ---------------- generic 128x128 tiled SGEMM ----------------
// C[M,N] = A[M,K] @ B[K,N]; M,N multiples of 128, K multiple of 16.
__global__ __launch_bounds__(256) void sgemm128(
    const float* __restrict__ A, const float* __restrict__ B,
    float* __restrict__ C, int M, int N, int K)
{
    __shared__ float As[16][128];
    __shared__ float Bs[16][128];
    const int tid = threadIdx.x;
    const int bm = blockIdx.y * 128, bn = blockIdx.x * 128;
    const int ty = tid >> 4, tx = tid & 15;

    float acc[8][8];
#pragma unroll
    for (int i = 0; i < 8; i++)
#pragma unroll
        for (int j = 0; j < 8; j++) acc[i][j] = 0.f;

    const int arow = tid >> 2;          // 0..63
    const int ak4 = (tid & 3) * 4;      // 0,4,8,12
    const int bcol = (tid & 31) * 4;    // 0..124
    const int bkk = tid >> 5;           // 0..7

    for (int k0 = 0; k0 < K; k0 += 16) {
#pragma unroll
        for (int it = 0; it < 2; it++) {
            int r = arow + it * 64;
            float4 va = *(const float4*)(A + (size_t)(bm + r) * K + k0 + ak4);
            As[ak4 + 0][r] = va.x; As[ak4 + 1][r] = va.y;
            As[ak4 + 2][r] = va.z; As[ak4 + 3][r] = va.w;
        }
#pragma unroll
        for (int it = 0; it < 2; it++) {
            int kk = bkk + it * 8;
            *(float4*)&Bs[kk][bcol] = *(const float4*)(B + (size_t)(k0 + kk) * N + bn + bcol);
        }
        __syncthreads();
#pragma unroll
        for (int kk = 0; kk < 16; kk++) {
            float a[8], b[8];
            *(float4*)&a[0] = *(const float4*)&As[kk][ty * 8];
            *(float4*)&a[4] = *(const float4*)&As[kk][ty * 8 + 4];
            *(float4*)&b[0] = *(const float4*)&Bs[kk][tx * 8];
            *(float4*)&b[4] = *(const float4*)&Bs[kk][tx * 8 + 4];
#pragma unroll
            for (int i = 0; i < 8; i++)
#pragma unroll
                for (int j = 0; j < 8; j++) acc[i][j] += a[i] * b[j];
        }
        __syncthreads();
    }
#pragma unroll
    for (int i = 0; i < 8; i++) {
        float4* cp = (float4*)(C + (size_t)(bm + ty * 8 + i) * N + bn + tx * 8);
        cp[0] = make_float4(acc[i][0], acc[i][1], acc[i][2], acc[i][3]);
        cp[1] = make_float4(acc[i][4], acc[i][5], acc[i][6], acc[i][7]);
    }
}

// ---------------- gates: x@{Wa,Wb,Walpha} + nonlinearities ----------------
__global__ void gates_kernel(
    const float* __restrict__ x,
    const float* __restrict__ Wa, const float* __restrict__ A_log,
    const float* __restrict__ dt_bias,
    const float* __restrict__ Wb, const float* __restrict__ bb,
    const float* __restrict__ Wal, const float* __restrict__ bal)
{
    __shared__ float xs[DMODEL];
    const int t = blockIdx.x;
    for (int i = threadIdx.x; i < DMODEL; i += blockDim.x)
        xs[i] = x[(size_t)t * DMODEL + i];
    __syncthreads();
    const int tid = threadIdx.x;
    if (tid < 48) {
        int grp = tid >> 4, h = tid & 15;
        const float* W = (grp == 0) ? Wa : ((grp == 1) ? Wb : Wal);
        float s = 0.f;
        for (int d = 0; d < DMODEL; d++) s += xs[d] * W[d * NHQ + h];
        if (grp == 0) {
            float z = s + dt_bias[h];
            float sp = (z > 20.f) ? z : log1pf(expf(z));
            g_glog[t * NHQ + h] = -expf(A_log[h]) * sp;
        } else if (grp == 1) {
            g_beta[t * NHQ + h] = 1.f / (1.f + expf(-(s + bb[h])));
        } else {
            g_alpha[t * NHQ + h] = 1.f / (1.f + expf(-(s + bal[h])));
        }
    }
}

// ---------------- causal depthwise conv(4) + silu ----------------
__global__ void conv_kernel(const float* __restrict__ in, const float* __restrict__ w,
                            float* __restrict__ out, int C, float scale)
{
    int idx = blockIdx.x * blockDim.x + threadIdx.x;
    if (idx >= LSEQ * C) return;
    int t = idx / C, c = idx % C;
    float s = 0.f;
#pragma unroll
    for (int j = 0; j < 4; j++) {
        int tj = t - 3 + j;
        if (tj >= 0) s += in[(size_t)tj * C + c] * w[c * 4 + j];
    }
    float y = s / (1.f + expf(-s));
    out[idx] = y * scale;
}

// ---------------- per-chunk inclusive cumsum of glog ----------------
__global__ void cs_kernel()
{
    int id = threadIdx.x;            // 256 = NHQ*NCHUNK
    int h = id >> 4, n = id & 15;
    float s = 0.f;
    for (int c = 0; c < CLEN; c++) {
        s += g_glog[(n * CLEN + c) * NHQ + h];
        g_cs[(h * NCHUNK + n) * CLEN + c] = s;
    }
    g_G[h * NCHUNK + n] = s;
    g_dgv[h * NCHUNK + n] = expf(s);
}

// ---------------- dH / dB gram increments, one block per (h,n) ----------------
__global__ __launch_bounds__(256, 1) void dhb_kernel()
{
    extern __shared__ float sm[];
    float* ks = sm;                  // 64*128
    float* vs = sm + CLEN * DHEAD;   // 64*128
    float* ws = sm + 2 * CLEN * DHEAD;
    const int mat = blockIdx.x;      // h*16+n
    const int h = mat >> 4, n = mat & 15, hk = h >> 1;
    const int tid = threadIdx.x;
    for (int i = tid; i < CLEN * DHEAD; i += 256) {
        int c = i >> 7, d = i & 127;
        int t = n * CLEN + c;
        ks[i] = g_k[t * 1024 + hk * DHEAD + d];
        vs[i] = g_v[t * 1024 + hk * DHEAD + d];
    }
    if (tid < CLEN) {
        float G = g_G[mat];
        float cs = g_cs[mat * CLEN + tid];
        ws[tid] = expf(G - cs) * g_beta[(n * CLEN + tid) * NHQ + h];
    }
    __syncthreads();
    const int ty = tid >> 4, tx = tid & 15;
    float dH[8][8], dB[8][8];
#pragma unroll
    for (int i = 0; i < 8; i++)
#pragma unroll
        for (int j = 0; j < 8; j++) { dH[i][j] = 0.f; dB[i][j] = 0.f; }

    for (int c = 0; c < CLEN; c++) {
        float w = ws[c];
        float ki[8], kj[8], vj[8];
        *(float4*)&ki[0] = *(const float4*)&ks[c * 128 + ty * 8];
        *(float4*)&ki[4] = *(const float4*)&ks[c * 128 + ty * 8 + 4];
        *(float4*)&kj[0] = *(const float4*)&ks[c * 128 + tx * 8];
        *(float4*)&kj[4] = *(const float4*)&ks[c * 128 + tx * 8 + 4];
        *(float4*)&vj[0] = *(const float4*)&vs[c * 128 + tx * 8];
        *(float4*)&vj[4] = *(const float4*)&vs[c * 128 + tx * 8 + 4];
#pragma unroll
        for (int i = 0; i < 8; i++) {
            float wk = w * ki[i];
#pragma unroll
            for (int j = 0; j < 8; j++) {
                dH[i][j] += wk * kj[j];
                dB[i][j] += wk * vj[j];
            }
        }
    }
    size_t base = (size_t)mat * DHEAD * DHEAD;
#pragma unroll
    for (int i = 0; i < 8; i++) {
        size_t off = base + (ty * 8 + i) * 128 + tx * 8;
        *(float4*)&g_dH[off]     = make_float4(dH[i][0], dH[i][1], dH[i][2], dH[i][3]);
        *(float4*)&g_dH[off + 4] = make_float4(dH[i][4], dH[i][5], dH[i][6], dH[i][7]);
        *(float4*)&g_dB[off]     = make_float4(dB[i][0], dB[i][1], dB[i][2], dB[i][3]);
        *(float4*)&g_dB[off + 4] = make_float4(dB[i][4], dB[i][5], dB[i][6], dB[i][7]);
    }
}

// ---------------- inter-chunk scan (elementwise over (h,d,e)) ----------------
__global__ void scan_kernel()
{
    int idx = blockIdx.x * blockDim.x + threadIdx.x;   // 16 * 16384
    int h = idx >> 14;
    int rem = idx & 16383;
    float hc = 0.f, bc = 0.f;
    for (int n = 0; n < NCHUNK; n++) {
        size_t off = (size_t)(h * NCHUNK + n) * 16384 + rem;
        g_H0[off] = hc;
        g_B0[off] = bc;
        float g = g_dgv[h * NCHUNK + n];
        hc = g * hc + g_dH[off];
        bc = g * bc + g_dB[off];
    }
}

// ---------------- Chebyshev solve, one block per matrix ----------------
__global__ __launch_bounds__(256, 1) void cheb_kernel()
{
    extern __shared__ float sm[];
    float* Ash = sm;             // 128*128
    float* dsh = sm + 16384;     // dvec
    float* rsh = sm + 32768;     // r
    __shared__ float red[128];
    __shared__ float s_lmax;
    const int mat = blockIdx.x;
    const int tid = threadIdx.x;
    const float* H0 = g_H0 + (size_t)mat * 16384;
    const float* B0p = g_B0 + (size_t)mat * 16384;

    for (int i = tid; i < 16384; i += 256) {
        float v = H0[i];
        if ((i >> 7) == (i & 127)) v += RIDGE_C;
        Ash[i] = v;
        rsh[i] = B0p[i];
    }
    __syncthreads();
    if (tid < 128) red[tid] = Ash[tid * 129];
    __syncthreads();
    for (int s = 64; s > 0; s >>= 1) {
        if (tid < s) red[tid] += red[tid + s];
        __syncthreads();
    }
    if (tid == 0) s_lmax = red[0];
    __syncthreads();

    const float lmax = s_lmax;
    const float theta = (lmax + RIDGE_C) * 0.5f;
    const float delta = (lmax - RIDGE_C) * 0.5f;
    const float sigma1 = theta / delta;
    float rho = 1.f / sigma1;
    const float inv_theta = 1.f / theta;
    for (int i = tid; i < 16384; i += 256) dsh[i] = rsh[i] * inv_theta;
    __syncthreads();

    const int ty = tid >> 4, tx = tid & 15;
    const int rb = ty * 8, cb = tx * 8;
    float x[8][8];
#pragma unroll
    for (int i = 0; i < 8; i++)
#pragma unroll
        for (int j = 0; j < 8; j++) x[i][j] = 0.f;

    for (int it = 0; it < NITER; it++) {
        float acc[8][8];
#pragma unroll
        for (int i = 0; i < 8; i++)
#pragma unroll
            for (int j = 0; j < 8; j++) acc[i][j] = 0.f;
        // acc = A @ dvec  (A symmetric: A[rb+i][e] == A[e][rb+i] -> vector loads)
        for (int e = 0; e < 128; e++) {
            float a[8], b[8];
            *(float4*)&a[0] = *(const float4*)&Ash[e * 128 + rb];
            *(float4*)&a[4] = *(const float4*)&Ash[e * 128 + rb + 4];
            *(float4*)&b[0] = *(const float4*)&dsh[e * 128 + cb];
            *(float4*)&b[4] = *(const float4*)&dsh[e * 128 + cb + 4];
#pragma unroll
            for (int i = 0; i < 8; i++)
#pragma unroll
                for (int j = 0; j < 8; j++) acc[i][j] += a[i] * b[j];
        }
        // x += dvec (own elements)
#pragma unroll
        for (int i = 0; i < 8; i++)
#pragma unroll
            for (int j = 0; j < 8; j++)
                x[i][j] += dsh[(rb + i) * 128 + cb + j];
        __syncthreads();
        float rho_n = 1.f / (2.f * sigma1 - rho);
        float c1 = rho_n * rho;
        float c2 = 2.f * rho_n / delta;
#pragma unroll
        for (int i = 0; i < 8; i++)
#pragma unroll
            for (int j = 0; j < 8; j++) {
                int off = (rb + i) * 128 + cb + j;
                float r = rsh[off] - acc[i][j];
                rsh[off] = r;
                dsh[off] = c1 * dsh[off] + c2 * r;
            }
        rho = rho_n;
        __syncthreads();
    }
    size_t base = (size_t)mat * 16384;
#pragma unroll
    for (int i = 0; i < 8; i++) {
        size_t off = base + (rb + i) * 128 + cb;
        *(float4*)&g_X[off]     = make_float4(x[i][0], x[i][1], x[i][2], x[i][3]);
        *(float4*)&g_X[off + 4] = make_float4(x[i][4], x[i][5], x[i][6], x[i][7]);
    }
}

// ---------------- o = exp(cs)*(q@X) + intra + alpha*v ----------------
__global__ __launch_bounds__(256, 1) void o_kernel()
{
    extern __shared__ float sm[];
    float* qs = sm;               // 64*128
    float* ks = sm + 8192;        // 64*128
    float* vs = sm + 16384;       // 64*128
    float* Xs = sm + 24576;       // 128*128
    float* Ss = sm + 40960;       // 64*64
    __shared__ float csh[CLEN], bsh[CLEN], ash[CLEN];
    const int mat = blockIdx.x;
    const int h = mat >> 4, n = mat & 15, hk = h >> 1;
    const int tid = threadIdx.x;

    for (int i = tid; i < CLEN * DHEAD; i += 256) {
        int c = i >> 7, d = i & 127;
        int t = n * CLEN + c;
        qs[i] = g_q[t * 2048 + h * DHEAD + d];
        ks[i] = g_k[t * 1024 + hk * DHEAD + d];
        vs[i] = g_v[t * 1024 + hk * DHEAD + d];
    }
    for (int i = tid; i < 16384; i += 256) Xs[i] = g_X[(size_t)mat * 16384 + i];
    if (tid < CLEN) {
        csh[tid] = g_cs[mat * CLEN + tid];
        int t = n * CLEN + tid;
        bsh[tid] = g_beta[t * NHQ + h];
        ash[tid] = g_alpha[t * NHQ + h];
    }
    __syncthreads();

    // masked gated scores
    for (int idx = tid; idx < 4096; idx += 256) {
        int c = idx >> 6, j = idx & 63;
        float s = 0.f;
        if (j <= c) {
            const float* qr = &qs[c * 128];
            const float* kr = &ks[j * 128];
            for (int d = 0; d < 128; d += 4) {
                s += qr[d] * kr[d] + qr[d + 1] * kr[d + 1]
                   + qr[d + 2] * kr[d + 2] + qr[d + 3] * kr[d + 3];
            }
            s *= expf(csh[c] - csh[j]) * bsh[j];
        }
        Ss[idx] = s;
    }
    __syncthreads();

    const int ty = tid >> 5, tx = tid & 31;   // 8 x 32
    const int r0 = ty * 8, f0 = tx * 4;
    float acc[8][4];
#pragma unroll
    for (int i = 0; i < 8; i++)
#pragma unroll
        for (int j = 0; j < 4; j++) acc[i][j] = 0.f;

    // inter: q @ X
    for (int d = 0; d < 128; d++) {
        float b[4];
        *(float4*)&b[0] = *(const float4*)&Xs[d * 128 + f0];
#pragma unroll
        for (int i = 0; i < 8; i++) {
            float a = qs[(r0 + i) * 128 + d];
#pragma unroll
            for (int j = 0; j < 4; j++) acc[i][j] += a * b[j];
        }
    }
#pragma unroll
    for (int i = 0; i < 8; i++) {
        float e = expf(csh[r0 + i]);
#pragma unroll
        for (int j = 0; j < 4; j++) acc[i][j] *= e;
    }
    // intra: S @ v
    for (int jc = 0; jc < CLEN; jc++) {
        float vv[4];
        *(float4*)&vv[0] = *(const float4*)&vs[jc * 128 + f0];
#pragma unroll
        for (int i = 0; i < 8; i++) {
            float s = Ss[(r0 + i) * 64 + jc];
#pragma unroll
            for (int j = 0; j < 4; j++) acc[i][j] += s * vv[j];
        }
    }
    // alpha * v + store
#pragma unroll
    for (int i = 0; i < 8; i++) {
        int c = r0 + i;
        int t = n * CLEN + c;
        float al = ash[c];
        float4 out;
        out.x = acc[i][0] + al * vs[c * 128 + f0 + 0];
        out.y = acc[i][1] + al * vs[c * 128 + f0 + 1];
        out.z = acc[i][2] + al * vs[c * 128 + f0 + 2];
        out.w = acc[i][3] + al * vs[c * 128 + f0 + 3];
        *(float4*)&g_o[(size_t)t * 2048 + h * DHEAD + f0] = out;
    }
}

// ---------------- gated RMSNorm ----------------
__global__ void rmsnorm_kernel(const float* __restrict__ norm_w)
{
    int warp = (blockIdx.x * blockDim.x + threadIdx.x) >> 5;
    int lane = threadIdx.x & 31;
    if (warp >= LSEQ * NHQ) return;
    int t = warp >> 4, h = warp & 15;
    const float* op = g_o + (size_t)warp * 128;
    float4 v = *(const float4*)(op + lane * 4);
    float ss = v.x * v.x + v.y * v.y + v.z * v.z + v.w * v.w;
#pragma unroll
    for (int off = 16; off > 0; off >>= 1)
        ss += __shfl_xor_sync(0xFFFFFFFFu, ss, off);
    float rms = rsqrtf(ss * (1.f / 128.f) + 1e-6f);
    int d = lane * 4;
    float4 gw = *(const float4*)(&g_gp[(size_t)t * 2048 + h * 128 + d]);
    float4 nw = *(const float4*)(norm_w + d);
    float4 o;
    o.x = v.x * rms * nw.x * (gw.x / (1.f + expf(-gw.x)));
    o.y = v.y * rms * nw.y * (gw.y / (1.f + expf(-gw.y)));
    o.z = v.z * rms * nw.z * (gw.z / (1.f + expf(-gw.z)));
    o.w = v.w * rms * nw.w * (gw.w / (1.f + expf(-gw.w)));
    *(float4*)&g_on[(size_t)warp * 128 + d] = o;
}

// ---------------- launch ----------------
extern "C" void kernel_launch(void* const* d_in, const int* in_sizes, int n_in,
                              void* d_out, int out_size)
{
    const float* x      = (const float*)d_in[0];
    const float* Wq     = (const float*)d_in[1];
    const float* Wk     = (const float*)d_in[2];
    const float* Wv     = (const float*)d_in[3];
    const float* conv_q = (const float*)d_in[4];
    const float* conv_k = (const float*)d_in[5];
    const float* conv_v = (const float*)d_in[6];
    const float* Wa     = (const float*)d_in[7];
    const float* A_log  = (const float*)d_in[8];
    const float* dt_b   = (const float*)d_in[9];
    const float* Wb     = (const float*)d_in[10];
    const float* bb     = (const float*)d_in[11];
    const float* Wal    = (const float*)d_in[12];
    const float* bal    = (const float*)d_in[13];
    const float* Wg     = (const float*)d_in[14];
    const float* norm_w = (const float*)d_in[15];
    const float* Wo     = (const float*)d_in[16];
    float* out = (float*)d_out;

    float *pq, *pk, *pv, *gp, *qb, *kb, *vb, *on;
    cudaGetSymbolAddress((void**)&pq, g_pq);
    cudaGetSymbolAddress((void**)&pk, g_pk);
    cudaGetSymbolAddress((void**)&pv, g_pv);
    cudaGetSymbolAddress((void**)&gp, g_gp);
    cudaGetSymbolAddress((void**)&qb, g_q);
    cudaGetSymbolAddress((void**)&kb, g_k);
    cudaGetSymbolAddress((void**)&vb, g_v);
    cudaGetSymbolAddress((void**)&on, g_on);

    cudaFuncSetAttribute(dhb_kernel, cudaFuncAttributeMaxDynamicSharedMemorySize, 65792);
    cudaFuncSetAttribute(cheb_kernel, cudaFuncAttributeMaxDynamicSharedMemorySize, 196608);
    cudaFuncSetAttribute(o_kernel, cudaFuncAttributeMaxDynamicSharedMemorySize, 180224);

    // 1. projections
    sgemm128<<<dim3(16, 8), 256>>>(x, Wq, pq, 1024, 2048, 2048);
    sgemm128<<<dim3(8, 8), 256>>>(x, Wk, pk, 1024, 1024, 2048);
    sgemm128<<<dim3(8, 8), 256>>>(x, Wv, pv, 1024, 1024, 2048);
    sgemm128<<<dim3(16, 8), 256>>>(x, Wg, gp, 1024, 2048, 2048);
    // 2. gates
    gates_kernel<<<1024, 64>>>(x, Wa, A_log, dt_b, Wb, bb, Wal, bal);
    // 3. convs (+silu; q gets d^-0.5)
    conv_kernel<<<8192, 256>>>(pq, conv_q, qb, 2048, 0.08838834764831843f);
    conv_kernel<<<4096, 256>>>(pk, conv_k, kb, 1024, 1.f);
    conv_kernel<<<4096, 256>>>(pv, conv_v, vb, 1024, 1.f);
    // 4. cumsum
    cs_kernel<<<1, 256>>>();
    // 5. gram increments
    dhb_kernel<<<256, 256, 65792>>>();
    // 6. chunk scan
    scan_kernel<<<1024, 256>>>();
    // 7. chebyshev solve
    cheb_kernel<<<256, 256, 196608>>>();
    // 8. inter + intra + alpha path
    o_kernel<<<256, 256, 180224>>>();
    // 9. gated rmsnorm
    rmsnorm_kernel<<<2048, 256>>>(norm_w);
    // 10. output projection
    sgemm128<<<dim3(16, 8), 256>>>(on, Wo, out, 1024, 2048, 2048);
}

// round 2
// speedup vs baseline: 1.2324x; 1.2324x over previous
#include <cuda_runtime.h>
#include <math.h>

#define LSEQ 1024
#define DMODEL 2048
#define NHQ 16
#define NHK 8
#define DHEAD 128
#define NCHUNK 16
#define CLEN 64
#define NITER 30
#define RIDGE_C 0.02f

typedef unsigned long long u64;

// ---------------- packed f32x2 helpers (sm_100+) ----------------
__device__ __forceinline__ u64 dup2(float a) {
    u64 r; asm("mov.b64 %0, {%1, %1};" : "=l"(r) : "f"(a)); return r;
}
__device__ __forceinline__ u64 pack2(float a, float b) {
    u64 r; asm("mov.b64 %0, {%1, %2};" : "=l"(r) : "f"(a), "f"(b)); return r;
}
__device__ __forceinline__ void ffma2(u64& c, u64 a, u64 b) {
    asm("fma.rn.f32x2 %0, %1, %2, %0;" : "+l"(c) : "l"(a), "l"(b));
}
__device__ __forceinline__ u64 ffma2r(u64 a, u64 b, u64 c) {
    u64 r; asm("fma.rn.f32x2 %0, %1, %2, %3;" : "=l"(r) : "l"(a), "l"(b), "l"(c)); return r;
}
__device__ __forceinline__ u64 mul2(u64 a, u64 b) {
    u64 r; asm("mul.rn.f32x2 %0, %1, %2;" : "=l"(r) : "l"(a), "l"(b)); return r;
}
__device__ __forceinline__ u64 add2(u64 a, u64 b) {
    u64 r; asm("add.rn.f32x2 %0, %1, %2;" : "=l"(r) : "l"(a), "l"(b)); return r;
}
__device__ __forceinline__ float2 unpk(u64 v) {
    float2 f; asm("mov.b64 {%0, %1}, %2;" : "=f"(f.x), "=f"(f.y) : "l"(v)); return f;
}

// ---------------- device scratch ----------------
__device__ float g_pq[LSEQ * 2048];
__device__ float g_pk[LSEQ * 1024];
__device__ float g_pv[LSEQ * 1024];
__device__ float g_q [LSEQ * 2048];
__device__ float g_k [LSEQ * 1024];
__device__ float g_v [LSEQ * 1024];
__device__ float g_gp[LSEQ * 2048];
__device__ float g_glog [LSEQ * NHQ];
__device__ float g_beta [LSEQ * NHQ];
__device__ float g_alpha[LSEQ * NHQ];
__device__ float g_cs[NHQ * NCHUNK * CLEN];
__device__ float g_G [NHQ * NCHUNK];
__device__ float g_dgv[NHQ * NCHUNK];
__device__ float g_dH[NHQ * NCHUNK * DHEAD * DHEAD];
__device__ float g_dB[NHQ * NCHUNK * DHEAD * DHEAD];
__device__ float g_H0[NHQ * NCHUNK * DHEAD * DHEAD];
__device__ float g_B0[NHQ * NCHUNK * DHEAD * DHEAD];
__device__ float g_X [NHQ * NCHUNK * DHEAD * DHEAD];
__device__ float g_o [LSEQ * NHQ * DHEAD];
__device__ float g_on[LSEQ * 2048];

// ---------------- shared GEMM core: 128x128 tile, FFMA2 inner ----------------
// C[bm:bm+128, bn:bn+128] = A[bm:,:K] @ B[:K, bn:], A stride K, B/C stride N.
__device__ __forceinline__ void gemm_core(
    const float* __restrict__ A, const float* __restrict__ B, float* __restrict__ C,
    int N, int K, int bm, int bn, float (*As)[128], float (*Bs)[128])
{
    const int tid = threadIdx.x;
    const int ty = tid >> 4, tx = tid & 15;

    u64 acc2[8][4];
#pragma unroll
    for (int i = 0; i < 8; i++)
#pragma unroll
        for (int j = 0; j < 4; j++) acc2[i][j] = 0ULL;

    const int arow = tid >> 2;          // 0..63
    const int ak4 = (tid & 3) * 4;      // 0,4,8,12
    const int bcol = (tid & 31) * 4;    // 0..124
    const int bkk = tid >> 5;           // 0..7

    for (int k0 = 0; k0 < K; k0 += 16) {
#pragma unroll
        for (int it = 0; it < 2; it++) {
            int r = arow + it * 64;
            float4 va = *(const float4*)(A + (size_t)(bm + r) * K + k0 + ak4);
            As[ak4 + 0][r] = va.x; As[ak4 + 1][r] = va.y;
            As[ak4 + 2][r] = va.z; As[ak4 + 3][r] = va.w;
        }
#pragma unroll
        for (int it = 0; it < 2; it++) {
            int kk = bkk + it * 8;
            *(float4*)&Bs[kk][bcol] = *(const float4*)(B + (size_t)(k0 + kk) * N + bn + bcol);
        }
        __syncthreads();
#pragma unroll
        for (int kk = 0; kk < 16; kk++) {
            float a[8];
            *(float4*)&a[0] = *(const float4*)&As[kk][ty * 8];
            *(float4*)&a[4] = *(const float4*)&As[kk][ty * 8 + 4];
            ulonglong2 b0 = *(const ulonglong2*)&Bs[kk][tx * 8];
            ulonglong2 b1 = *(const ulonglong2*)&Bs[kk][tx * 8 + 4];
            u64 b2[4] = {b0.x, b0.y, b1.x, b1.y};
#pragma unroll
            for (int i = 0; i < 8; i++) {
                u64 ad = dup2(a[i]);
#pragma unroll
                for (int j = 0; j < 4; j++) ffma2(acc2[i][j], ad, b2[j]);
            }
        }
        __syncthreads();
    }
#pragma unroll
    for (int i = 0; i < 8; i++) {
        float2 p0 = unpk(acc2[i][0]), p1 = unpk(acc2[i][1]);
        float2 p2 = unpk(acc2[i][2]), p3 = unpk(acc2[i][3]);
        float4* cp = (float4*)(C + (size_t)(bm + ty * 8 + i) * N + bn + tx * 8);
        cp[0] = make_float4(p0.x, p0.y, p1.x, p1.y);
        cp[1] = make_float4(p2.x, p2.y, p3.x, p3.y);
    }
}

// generic GEMM (used for final output projection)
__global__ __launch_bounds__(256) void sgemm128(
    const float* __restrict__ A, const float* __restrict__ B,
    float* __restrict__ C, int N, int K)
{
    __shared__ float As[16][128];
    __shared__ float Bs[16][128];
    gemm_core(A, B, C, N, K, blockIdx.y * 128, blockIdx.x * 128, As, Bs);
}

// fused q/k/v/g projection GEMM: x @ {Wq, Wk, Wv, Wg} in one launch
__global__ __launch_bounds__(256) void proj_kernel(
    const float* __restrict__ x,
    const float* __restrict__ Wq, const float* __restrict__ Wk,
    const float* __restrict__ Wv, const float* __restrict__ Wg)
{
    __shared__ float As[16][128];
    __shared__ float Bs[16][128];
    const int bx = blockIdx.x;
    const float* B; float* C; int N, bn;
    if (bx < 16)      { B = Wq; C = g_pq; N = 2048; bn = bx * 128; }
    else if (bx < 24) { B = Wk; C = g_pk; N = 1024; bn = (bx - 16) * 128; }
    else if (bx < 32) { B = Wv; C = g_pv; N = 1024; bn = (bx - 24) * 128; }
    else              { B = Wg; C = g_gp; N = 2048; bn = (bx - 32) * 128; }
    gemm_core(x, B, C, N, DMODEL, blockIdx.y * 128, bn, As, Bs);
}

// ---------------- gates: x@{Wa,Wb,Walpha} + nonlinearities ----------------
__global__ void gates_kernel(
    const float* __restrict__ x,
    const float* __restrict__ Wa, const float* __restrict__ A_log,
    const float* __restrict__ dt_bias,
    const float* __restrict__ Wb, const float* __restrict__ bb,
    const float* __restrict__ Wal, const float* __restrict__ bal)
{
    __shared__ float xs[DMODEL];
    const int t = blockIdx.x;
    for (int i = threadIdx.x; i < DMODEL; i += blockDim.x)
        xs[i] = x[(size_t)t * DMODEL + i];
    __syncthreads();
    const int tid = threadIdx.x;
    if (tid < 48) {
        int grp = tid >> 4, h = tid & 15;
        const float* W = (grp == 0) ? Wa : ((grp == 1) ? Wb : Wal);
        float s = 0.f;
        for (int d = 0; d < DMODEL; d++) s += xs[d] * W[d * NHQ + h];
        if (grp == 0) {
            float z = s + dt_bias[h];
            float sp = (z > 20.f) ? z : log1pf(expf(z));
            g_glog[t * NHQ + h] = -expf(A_log[h]) * sp;
        } else if (grp == 1) {
            g_beta[t * NHQ + h] = 1.f / (1.f + expf(-(s + bb[h])));
        } else {
            g_alpha[t * NHQ + h] = 1.f / (1.f + expf(-(s + bal[h])));
        }
    }
}

// ---------------- causal depthwise conv(4) + silu ----------------
__global__ void conv_kernel(const float* __restrict__ in, const float* __restrict__ w,
                            float* __restrict__ out, int C, float scale)
{
    int idx = blockIdx.x * blockDim.x + threadIdx.x;
    if (idx >= LSEQ * C) return;
    int t = idx / C, c = idx % C;
    float s = 0.f;
#pragma unroll
    for (int j = 0; j < 4; j++) {
        int tj = t - 3 + j;
        if (tj >= 0) s += in[(size_t)tj * C + c] * w[c * 4 + j];
    }
    float y = s / (1.f + expf(-s));
    out[idx] = y * scale;
}

// ---------------- per-chunk inclusive cumsum of glog ----------------
__global__ void cs_kernel()
{
    int id = threadIdx.x;            // 256 = NHQ*NCHUNK
    int h = id >> 4, n = id & 15;
    float s = 0.f;
    for (int c = 0; c < CLEN; c++) {
        s += g_glog[(n * CLEN + c) * NHQ + h];
        g_cs[(h * NCHUNK + n) * CLEN + c] = s;
    }
    g_G[h * NCHUNK + n] = s;
    g_dgv[h * NCHUNK + n] = expf(s);
}

// ---------------- dH / dB gram increments, one block per (h,n) ----------------
__global__ __launch_bounds__(256, 1) void dhb_kernel()
{
    extern __shared__ float sm[];
    float* ks = sm;                  // 64*128
    float* vs = sm + CLEN * DHEAD;   // 64*128
    float* ws = sm + 2 * CLEN * DHEAD;
    const int mat = blockIdx.x;      // h*16+n
    const int h = mat >> 4, n = mat & 15, hk = h >> 1;
    const int tid = threadIdx.x;
    for (int i = tid; i < CLEN * DHEAD; i += 256) {
        int c = i >> 7, d = i & 127;
        int t = n * CLEN + c;
        ks[i] = g_k[t * 1024 + hk * DHEAD + d];
        vs[i] = g_v[t * 1024 + hk * DHEAD + d];
    }
    if (tid < CLEN) {
        float G = g_G[mat];
        float cs = g_cs[mat * CLEN + tid];
        ws[tid] = expf(G - cs) * g_beta[(n * CLEN + tid) * NHQ + h];
    }
    __syncthreads();
    const int ty = tid >> 4, tx = tid & 15;
    u64 dH2[8][4], dB2[8][4];
#pragma unroll
    for (int i = 0; i < 8; i++)
#pragma unroll
        for (int j = 0; j < 4; j++) { dH2[i][j] = 0ULL; dB2[i][j] = 0ULL; }

    for (int c = 0; c < CLEN; c++) {
        float w = ws[c];
        float ki[8];
        *(float4*)&ki[0] = *(const float4*)&ks[c * 128 + ty * 8];
        *(float4*)&ki[4] = *(const float4*)&ks[c * 128 + ty * 8 + 4];
        ulonglong2 k0 = *(const ulonglong2*)&ks[c * 128 + tx * 8];
        ulonglong2 k1 = *(const ulonglong2*)&ks[c * 128 + tx * 8 + 4];
        ulonglong2 v0 = *(const ulonglong2*)&vs[c * 128 + tx * 8];
        ulonglong2 v1 = *(const ulonglong2*)&vs[c * 128 + tx * 8 + 4];
        u64 kj2[4] = {k0.x, k0.y, k1.x, k1.y};
        u64 vj2[4] = {v0.x, v0.y, v1.x, v1.y};
#pragma unroll
        for (int i = 0; i < 8; i++) {
            u64 wk = dup2(w * ki[i]);
#pragma unroll
            for (int j = 0; j < 4; j++) {
                ffma2(dH2[i][j], wk, kj2[j]);
                ffma2(dB2[i][j], wk, vj2[j]);
            }
        }
    }
    size_t base = (size_t)mat * DHEAD * DHEAD;
#pragma unroll
    for (int i = 0; i < 8; i++) {
        size_t off = base + (ty * 8 + i) * 128 + tx * 8;
        float2 h0 = unpk(dH2[i][0]), h1 = unpk(dH2[i][1]);
        float2 h2 = unpk(dH2[i][2]), h3 = unpk(dH2[i][3]);
        *(float4*)&g_dH[off]     = make_float4(h0.x, h0.y, h1.x, h1.y);
        *(float4*)&g_dH[off + 4] = make_float4(h2.x, h2.y, h3.x, h3.y);
        float2 b0 = unpk(dB2[i][0]), b1 = unpk(dB2[i][1]);
        float2 b2 = unpk(dB2[i][2]), b3 = unpk(dB2[i][3]);
        *(float4*)&g_dB[off]     = make_float4(b0.x, b0.y, b1.x, b1.y);
        *(float4*)&g_dB[off + 4] = make_float4(b2.x, b2.y, b3.x, b3.y);
    }
}

// ---------------- inter-chunk scan (elementwise over (h,d,e)) ----------------
__global__ void scan_kernel()
{
    int idx = blockIdx.x * blockDim.x + threadIdx.x;   // 16 * 16384
    int h = idx >> 14;
    int rem = idx & 16383;
    float hc = 0.f, bc = 0.f;
    for (int n = 0; n < NCHUNK; n++) {
        size_t off = (size_t)(h * NCHUNK + n) * 16384 + rem;
        g_H0[off] = hc;
        g_B0[off] = bc;
        float g = g_dgv[h * NCHUNK + n];
        hc = g * hc + g_dH[off];
        bc = g * bc + g_dB[off];
    }
}

// ---------------- Chebyshev solve, one block per matrix ----------------
__global__ __launch_bounds__(256, 1) void cheb_kernel()
{
    extern __shared__ float sm[];
    float* Ash = sm;             // 128*128
    float* dsh = sm + 16384;     // dvec
    float* rsh = sm + 32768;     // r
    __shared__ float red[128];
    __shared__ float s_lmax;
    const int mat = blockIdx.x;
    const int tid = threadIdx.x;
    const float* H0 = g_H0 + (size_t)mat * 16384;
    const float* B0p = g_B0 + (size_t)mat * 16384;

    for (int i = tid; i < 16384; i += 256) {
        float v = H0[i];
        if ((i >> 7) == (i & 127)) v += RIDGE_C;
        Ash[i] = v;
        rsh[i] = B0p[i];
    }
    __syncthreads();
    if (tid < 128) red[tid] = Ash[tid * 129];
    __syncthreads();
    for (int s = 64; s > 0; s >>= 1) {
        if (tid < s) red[tid] += red[tid + s];
        __syncthreads();
    }
    if (tid == 0) s_lmax = red[0];
    __syncthreads();

    const float lmax = s_lmax;
    const float theta = (lmax + RIDGE_C) * 0.5f;
    const float delta = (lmax - RIDGE_C) * 0.5f;
    const float sigma1 = theta / delta;
    float rho = 1.f / sigma1;
    const float inv_theta = 1.f / theta;
    for (int i = tid; i < 16384; i += 256) dsh[i] = rsh[i] * inv_theta;
    __syncthreads();

    const int ty = tid >> 4, tx = tid & 15;
    const int rb = ty * 8, cb = tx * 8;
    u64 x2[8][4];
#pragma unroll
    for (int i = 0; i < 8; i++)
#pragma unroll
        for (int j = 0; j < 4; j++) x2[i][j] = 0ULL;

    const u64 neg1 = dup2(-1.f);

    for (int it = 0; it < NITER; it++) {
        u64 acc2[8][4];
#pragma unroll
        for (int i = 0; i < 8; i++)
#pragma unroll
            for (int j = 0; j < 4; j++) acc2[i][j] = 0ULL;
        // acc = A @ dvec  (A symmetric: read row e for column-vector loads)
        for (int e = 0; e < 128; e++) {
            float a[8];
            *(float4*)&a[0] = *(const float4*)&Ash[e * 128 + rb];
            *(float4*)&a[4] = *(const float4*)&Ash[e * 128 + rb + 4];
            ulonglong2 d0 = *(const ulonglong2*)&dsh[e * 128 + cb];
            ulonglong2 d1 = *(const ulonglong2*)&dsh[e * 128 + cb + 4];
            u64 b2[4] = {d0.x, d0.y, d1.x, d1.y};
#pragma unroll
            for (int i = 0; i < 8; i++) {
                u64 ad = dup2(a[i]);
#pragma unroll
                for (int j = 0; j < 4; j++) ffma2(acc2[i][j], ad, b2[j]);
            }
        }
        // x += dvec (own tile)
#pragma unroll
        for (int i = 0; i < 8; i++) {
            const u64* dp = (const u64*)&dsh[(rb + i) * 128 + cb];
#pragma unroll
            for (int j = 0; j < 4; j++) x2[i][j] = add2(x2[i][j], dp[j]);
        }
        __syncthreads();
        float rho_n = 1.f / (2.f * sigma1 - rho);
        const u64 c1 = dup2(rho_n * rho);
        const u64 c2 = dup2(2.f * rho_n / delta);
#pragma unroll
        for (int i = 0; i < 8; i++) {
            u64* rp = (u64*)&rsh[(rb + i) * 128 + cb];
            u64* dp = (u64*)&dsh[(rb + i) * 128 + cb];
#pragma unroll
            for (int j = 0; j < 4; j++) {
                u64 r2 = ffma2r(acc2[i][j], neg1, rp[j]);   // r - A@d
                rp[j] = r2;
                dp[j] = ffma2r(c2, r2, mul2(c1, dp[j]));    // c1*d + c2*r
            }
        }
        rho = rho_n;
        __syncthreads();
    }
    size_t base = (size_t)mat * 16384;
#pragma unroll
    for (int i = 0; i < 8; i++) {
        size_t off = base + (rb + i) * 128 + cb;
        float2 p0 = unpk(x2[i][0]), p1 = unpk(x2[i][1]);
        float2 p2 = unpk(x2[i][2]), p3 = unpk(x2[i][3]);
        *(float4*)&g_X[off]     = make_float4(p0.x, p0.y, p1.x, p1.y);
        *(float4*)&g_X[off + 4] = make_float4(p2.x, p2.y, p3.x, p3.y);
    }
}

// ---------------- o = exp(cs)*(q@X) + intra + alpha*v ----------------
__global__ __launch_bounds__(256, 1) void o_kernel()
{
    extern __shared__ float sm[];
    float* qs = sm;               // 64*128
    float* ks = sm + 8192;        // 64*128
    float* vs = sm + 16384;       // 64*128
    float* Xs = sm + 24576;       // 128*128
    float* Ss = sm + 40960;       // 64*64
    __shared__ float csh[CLEN], bsh[CLEN], ash[CLEN];
    const int mat = blockIdx.x;
    const int h = mat >> 4, n = mat & 15, hk = h >> 1;
    const int tid = threadIdx.x;

    for (int i = tid; i < CLEN * DHEAD; i += 256) {
        int c = i >> 7, d = i & 127;
        int t = n * CLEN + c;
        qs[i] = g_q[t * 2048 + h * DHEAD + d];
        ks[i] = g_k[t * 1024 + hk * DHEAD + d];
        vs[i] = g_v[t * 1024 + hk * DHEAD + d];
    }
    for (int i = tid; i < 16384; i += 256) Xs[i] = g_X[(size_t)mat * 16384 + i];
    if (tid < CLEN) {
        csh[tid] = g_cs[mat * CLEN + tid];
        int t = n * CLEN + tid;
        bsh[tid] = g_beta[t * NHQ + h];
        ash[tid] = g_alpha[t * NHQ + h];
    }
    __syncthreads();

    // masked gated scores
    for (int idx = tid; idx < 4096; idx += 256) {
        int c = idx >> 6, j = idx & 63;
        float s = 0.f;
        if (j <= c) {
            const float* qr = &qs[c * 128];
            const float* kr = &ks[j * 128];
            for (int d = 0; d < 128; d += 4) {
                s += qr[d] * kr[d] + qr[d + 1] * kr[d + 1]
                   + qr[d + 2] * kr[d + 2] + qr[d + 3] * kr[d + 3];
            }
            s *= expf(csh[c] - csh[j]) * bsh[j];
        }
        Ss[idx] = s;
    }
    __syncthreads();

    const int ty = tid >> 5, tx = tid & 31;   // 8 x 32
    const int r0 = ty * 8, f0 = tx * 4;
    u64 acc2[8][2];
#pragma unroll
    for (int i = 0; i < 8; i++) { acc2[i][0] = 0ULL; acc2[i][1] = 0ULL; }

    // inter: q @ X
    for (int d = 0; d < 128; d++) {
        ulonglong2 bb = *(const ulonglong2*)&Xs[d * 128 + f0];
#pragma unroll
        for (int i = 0; i < 8; i++) {
            u64 ad = dup2(qs[(r0 + i) * 128 + d]);
            ffma2(acc2[i][0], ad, bb.x);
            ffma2(acc2[i][1], ad, bb.y);
        }
    }
#pragma unroll
    for (int i = 0; i < 8; i++) {
        u64 e = dup2(expf(csh[r0 + i]));
        acc2[i][0] = mul2(acc2[i][0], e);
        acc2[i][1] = mul2(acc2[i][1], e);
    }
    // intra: S @ v
    for (int jc = 0; jc < CLEN; jc++) {
        ulonglong2 vv = *(const ulonglong2*)&vs[jc * 128 + f0];
#pragma unroll
        for (int i = 0; i < 8; i++) {
            u64 sd = dup2(Ss[(r0 + i) * 64 + jc]);
            ffma2(acc2[i][0], sd, vv.x);
            ffma2(acc2[i][1], sd, vv.y);
        }
    }
    // alpha * v + store
#pragma unroll
    for (int i = 0; i < 8; i++) {
        int c = r0 + i;
        int t = n * CLEN + c;
        u64 al = dup2(ash[c]);
        ulonglong2 vv = *(const ulonglong2*)&vs[c * 128 + f0];
        u64 o0 = ffma2r(al, vv.x, acc2[i][0]);
        u64 o1 = ffma2r(al, vv.y, acc2[i][1]);
        float2 p0 = unpk(o0), p1 = unpk(o1);
        *(float4*)&g_o[(size_t)t * 2048 + h * DHEAD + f0] =
            make_float4(p0.x, p0.y, p1.x, p1.y);
    }
}

// ---------------- gated RMSNorm ----------------
__global__ void rmsnorm_kernel(const float* __restrict__ norm_w)
{
    int warp = (blockIdx.x * blockDim.x + threadIdx.x) >> 5;
    int lane = threadIdx.x & 31;
    if (warp >= LSEQ * NHQ) return;
    int t = warp >> 4, h = warp & 15;
    const float* op = g_o + (size_t)warp * 128;
    float4 v = *(const float4*)(op + lane * 4);
    float ss = v.x * v.x + v.y * v.y + v.z * v.z + v.w * v.w;
#pragma unroll
    for (int off = 16; off > 0; off >>= 1)
        ss += __shfl_xor_sync(0xFFFFFFFFu, ss, off);
    float rms = rsqrtf(ss * (1.f / 128.f) + 1e-6f);
    int d = lane * 4;
    float4 gw = *(const float4*)(&g_gp[(size_t)t * 2048 + h * 128 + d]);
    float4 nw = *(const float4*)(norm_w + d);
    float4 o;
    o.x = v.x * rms * nw.x * (gw.x / (1.f + expf(-gw.x)));
    o.y = v.y * rms * nw.y * (gw.y / (1.f + expf(-gw.y)));
    o.z = v.z * rms * nw.z * (gw.z / (1.f + expf(-gw.z)));
    o.w = v.w * rms * nw.w * (gw.w / (1.f + expf(-gw.w)));
    *(float4*)&g_on[(size_t)warp * 128 + d] = o;
}

// ---------------- launch ----------------
extern "C" void kernel_launch(void* const* d_in, const int* in_sizes, int n_in,
                              void* d_out, int out_size)
{
    const float* x      = (const float*)d_in[0];
    const float* Wq     = (const float*)d_in[1];
    const float* Wk     = (const float*)d_in[2];
    const float* Wv     = (const float*)d_in[3];
    const float* conv_q = (const float*)d_in[4];
    const float* conv_k = (const float*)d_in[5];
    const float* conv_v = (const float*)d_in[6];
    const float* Wa     = (const float*)d_in[7];
    const float* A_log  = (const float*)d_in[8];
    const float* dt_b   = (const float*)d_in[9];
    const float* Wb     = (const float*)d_in[10];
    const float* bb     = (const float*)d_in[11];
    const float* Wal    = (const float*)d_in[12];
    const float* bal    = (const float*)d_in[13];
    const float* Wg     = (const float*)d_in[14];
    const float* norm_w = (const float*)d_in[15];
    const float* Wo     = (const float*)d_in[16];
    float* out = (float*)d_out;

    float *pq, *pk, *pv, *qb, *kb, *vb, *on;
    cudaGetSymbolAddress((void**)&pq, g_pq);
    cudaGetSymbolAddress((void**)&pk, g_pk);
    cudaGetSymbolAddress((void**)&pv, g_pv);
    cudaGetSymbolAddress((void**)&qb, g_q);
    cudaGetSymbolAddress((void**)&kb, g_k);
    cudaGetSymbolAddress((void**)&vb, g_v);
    cudaGetSymbolAddress((void**)&on, g_on);

    cudaFuncSetAttribute(dhb_kernel, cudaFuncAttributeMaxDynamicSharedMemorySize, 65792);
    cudaFuncSetAttribute(cheb_kernel, cudaFuncAttributeMaxDynamicSharedMemorySize, 196608);
    cudaFuncSetAttribute(o_kernel, cudaFuncAttributeMaxDynamicSharedMemorySize, 180224);

    // 1. fused projections (q,k,v,g) in one launch
    proj_kernel<<<dim3(48, 8), 256>>>(x, Wq, Wk, Wv, Wg);
    // 2. gates
    gates_kernel<<<1024, 64>>>(x, Wa, A_log, dt_b, Wb, bb, Wal, bal);
    // 3. convs (+silu; q gets d^-0.5)
    conv_kernel<<<8192, 256>>>(pq, conv_q, qb, 2048, 0.08838834764831843f);
    conv_kernel<<<4096, 256>>>(pk, conv_k, kb, 1024, 1.f);
    conv_kernel<<<4096, 256>>>(pv, conv_v, vb, 1024, 1.f);
    // 4. cumsum
    cs_kernel<<<1, 256>>>();
    // 5. gram increments
    dhb_kernel<<<256, 256, 65792>>>();
    // 6. chunk scan
    scan_kernel<<<1024, 256>>>();
    // 7. chebyshev solve
    cheb_kernel<<<256, 256, 196608>>>();
    // 8. inter + intra + alpha path
    o_kernel<<<256, 256, 180224>>>();
    // 9. gated rmsnorm
    rmsnorm_kernel<<<2048, 256>>>(norm_w);
    // 10. output projection
    sgemm128<<<dim3(16, 8), 256>>>(on, Wo, out, 2048, 2048);
}